// round 1
// baseline (speedup 1.0000x reference)
#include <cuda_runtime.h>
#include <math.h>

#define B_  4
#define C_  256
#define N_  4096
#define CQ_ 64

// ---------------- scratch (static __device__ — no allocations allowed) ---------
__device__ float g_P[B_*CQ_*N_];     // P = w_qk @ x          (4 MB)
__device__ float g_V[B_*C_*N_];      // V = w_v @ x + b_v     (16 MB)
__device__ float g_M[B_*C_*N_];      // unnormalized V @ A    (16 MB)
__device__ float g_R[B_*C_*N_];      // x - nf                (16 MB)
__device__ float g_rowmax[B_*N_];
__device__ float g_rowsum[B_*N_];
__device__ float g_colsum[B_*N_];

// ---------------- generic batched SGEMM: C[b] = A(Mx256) * X[b](256xN_) --------
// BM=64, BN=128, BK=16, 256 threads, 8x4 micro-tile.
// mode 0: none; mode 1: +bias; mode 2: +bias, BN(inference), ReLU
__global__ __launch_bounds__(256) void gemm_kernel(
    const float* __restrict__ A,
    const float* __restrict__ X, long long xstride,
    float* __restrict__ Co, long long cstride,
    int mode,
    const float* __restrict__ bias,
    const float* __restrict__ gamma, const float* __restrict__ beta,
    const float* __restrict__ mean,  const float* __restrict__ var)
{
    __shared__ float As[16][65];
    __shared__ float Bs[16][132];
    const int t  = threadIdx.x;
    const int n0 = blockIdx.x * 128;
    const int m0 = blockIdx.y * 64;
    const float* Xb = X + (long long)blockIdx.z * xstride;
    float*       Cb = Co + (long long)blockIdx.z * cstride;
    const int r0 = (t >> 5) << 3;     // 0..56
    const int c0 = (t & 31) << 2;     // 0..124

    float acc[8][4];
#pragma unroll
    for (int i = 0; i < 8; i++)
#pragma unroll
        for (int j = 0; j < 4; j++) acc[i][j] = 0.f;

    for (int k0 = 0; k0 < 256; k0 += 16) {
        {   // A tile 64x16 -> As[k][m]
            int row = t >> 2, kc = (t & 3) << 2;
            float4 v = *(const float4*)(A + (m0 + row) * 256 + k0 + kc);
            As[kc + 0][row] = v.x; As[kc + 1][row] = v.y;
            As[kc + 2][row] = v.z; As[kc + 3][row] = v.w;
        }
        {   // B tile 16x128
            int kr = t >> 5, col = (t & 31) << 2;
            *(float4*)&Bs[kr][col]     = *(const float4*)(Xb + (long long)(k0 + kr)     * N_ + n0 + col);
            *(float4*)&Bs[kr + 8][col] = *(const float4*)(Xb + (long long)(k0 + kr + 8) * N_ + n0 + col);
        }
        __syncthreads();
#pragma unroll
        for (int k = 0; k < 16; k++) {
            float a[8];
#pragma unroll
            for (int i = 0; i < 8; i++) a[i] = As[k][r0 + i];
            float4 bv = *(float4*)&Bs[k][c0];
            float bb[4] = {bv.x, bv.y, bv.z, bv.w};
#pragma unroll
            for (int i = 0; i < 8; i++)
#pragma unroll
                for (int j = 0; j < 4; j++) acc[i][j] += a[i] * bb[j];
        }
        __syncthreads();
    }

#pragma unroll
    for (int i = 0; i < 8; i++) {
        int m = m0 + r0 + i;
        float v[4] = {acc[i][0], acc[i][1], acc[i][2], acc[i][3]};
        if (mode >= 1) {
            float bb = bias[m];
#pragma unroll
            for (int j = 0; j < 4; j++) v[j] += bb;
        }
        if (mode == 2) {
            float sc = gamma[m] * rsqrtf(var[m] + 1e-5f);
            float mu = mean[m], bt = beta[m];
#pragma unroll
            for (int j = 0; j < 4; j++) v[j] = fmaxf((v[j] - mu) * sc + bt, 0.f);
        }
        *(float4*)&Cb[(long long)m * N_ + n0 + c0] = make_float4(v[0], v[1], v[2], v[3]);
    }
}

// ---------------- pass 1: per-row online (max, sum) of scores = P^T P ----------
// block: 128 rows (n), loops over 32 m-tiles of 128. 16x16 threads, 8x8 micro.
__global__ __launch_bounds__(256) void rowstats_kernel()
{
    extern __shared__ float sh[];
    float* Pn  = sh;                 // [64][132]
    float* Pm  = sh + 64 * 132;      // [64][132]
    float* red = sh + 2 * 64 * 132;  // [128][32]
    const int t  = threadIdx.x;
    const int n0 = blockIdx.x * 128;
    const int b  = blockIdx.y;
    const float* P = g_P + (long long)b * CQ_ * N_;

#pragma unroll
    for (int i = 0; i < 8; i++) {
        int idx = t + i * 256; int q = idx >> 5, col = (idx & 31) << 2;
        *(float4*)&Pn[q * 132 + col] = *(const float4*)(P + (long long)q * N_ + n0 + col);
    }

    const int r0 = (t >> 4) << 3;   // 0..120 (n rows)
    const int c0 = (t & 15) << 3;   // 0..120 (m cols)
    float mx[8], sm_[8];
#pragma unroll
    for (int i = 0; i < 8; i++) { mx[i] = -1e30f; sm_[i] = 0.f; }

    for (int m0 = 0; m0 < N_; m0 += 128) {
        __syncthreads();
#pragma unroll
        for (int i = 0; i < 8; i++) {
            int idx = t + i * 256; int q = idx >> 5, col = (idx & 31) << 2;
            *(float4*)&Pm[q * 132 + col] = *(const float4*)(P + (long long)q * N_ + m0 + col);
        }
        __syncthreads();

        float s[8][8];
#pragma unroll
        for (int i = 0; i < 8; i++)
#pragma unroll
            for (int j = 0; j < 8; j++) s[i][j] = 0.f;

#pragma unroll
        for (int k = 0; k < 64; k++) {
            float4 a0 = *(float4*)&Pn[k * 132 + r0];
            float4 a1 = *(float4*)&Pn[k * 132 + r0 + 4];
            float4 b0 = *(float4*)&Pm[k * 132 + c0];
            float4 b1 = *(float4*)&Pm[k * 132 + c0 + 4];
            float av[8] = {a0.x, a0.y, a0.z, a0.w, a1.x, a1.y, a1.z, a1.w};
            float bv[8] = {b0.x, b0.y, b0.z, b0.w, b1.x, b1.y, b1.z, b1.w};
#pragma unroll
            for (int i = 0; i < 8; i++)
#pragma unroll
                for (int j = 0; j < 8; j++) s[i][j] += av[i] * bv[j];
        }
#pragma unroll
        for (int i = 0; i < 8; i++) {
            float tm = s[i][0];
#pragma unroll
            for (int j = 1; j < 8; j++) tm = fmaxf(tm, s[i][j]);
            float nm = fmaxf(mx[i], tm);
            float add = 0.f;
#pragma unroll
            for (int j = 0; j < 8; j++) add += __expf(s[i][j] - nm);
            sm_[i] = sm_[i] * __expf(mx[i] - nm) + add;
            mx[i] = nm;
        }
    }
    __syncthreads();
#pragma unroll
    for (int i = 0; i < 8; i++) {
        red[(r0 + i) * 32 + (t & 15) * 2]     = mx[i];
        red[(r0 + i) * 32 + (t & 15) * 2 + 1] = sm_[i];
    }
    __syncthreads();
    if (t < 128) {
        float M = -1e30f, S = 0.f;
#pragma unroll
        for (int j = 0; j < 16; j++) {
            float m2 = red[t * 32 + j * 2], s2 = red[t * 32 + j * 2 + 1];
            float nm = fmaxf(M, m2);
            S = S * __expf(M - nm) + s2 * __expf(m2 - nm);
            M = nm;
        }
        g_rowmax[b * N_ + n0 + t] = M;
        g_rowsum[b * N_ + n0 + t] = S;
    }
}

// ---------------- pass 2: fused score-recompute + exp + V@A + colsum -----------
// grid (chalf=2, mtile=32, b=4). block computes M[128 c][128 m] + colsum[128 m].
__global__ __launch_bounds__(256, 1) void attn_out_kernel()
{
    extern __shared__ float sh[];
    float* Pm    = sh;                           // [64][132] P[:, m-tile]
    float* Pn    = Pm  + 64 * 132;               // [64][68]  P[:, n-tile]
    float* Aexp  = Pn  + 64 * 68;                // [64][132] exp'd scores
    float* Vs    = Aexp + 64 * 132;              // [128][68] V[c-tile, n-tile]
    float* stats = Vs  + 128 * 68;               // [64*2] (rowmax, 1/rowsum)

    const int t     = threadIdx.x;
    const int chalf = blockIdx.x;
    const int m0    = blockIdx.y * 128;
    const int b     = blockIdx.z;
    const int ct0   = chalf * 128;
    const float* P = g_P + (long long)b * CQ_ * N_;
    const float* V = g_V + (long long)b * C_  * N_;

#pragma unroll
    for (int i = 0; i < 8; i++) {   // Pm once
        int idx = t + i * 256; int q = idx >> 5, col = (idx & 31) << 2;
        *(float4*)&Pm[q * 132 + col] = *(const float4*)(P + (long long)q * N_ + m0 + col);
    }

    const int rs = (t >> 4) << 2;   // s-phase rows (n), 4 each
    const int cs = (t & 15) << 3;   // cols (m), 8 each
    const int rg = (t >> 4) << 3;   // gemm2 rows (c), 8 each

    float acc[8][8];
#pragma unroll
    for (int i = 0; i < 8; i++)
#pragma unroll
        for (int j = 0; j < 8; j++) acc[i][j] = 0.f;
    float csum = 0.f;

    for (int n0 = 0; n0 < N_; n0 += 64) {
        __syncthreads();
#pragma unroll
        for (int i = 0; i < 4; i++) {   // Pn 64x64
            int idx = t + i * 256; int q = idx >> 4, kc = (idx & 15) << 2;
            *(float4*)&Pn[q * 68 + kc] = *(const float4*)(P + (long long)q * N_ + n0 + kc);
        }
#pragma unroll
        for (int i = 0; i < 8; i++) {   // Vs 128x64
            int idx = t + i * 256; int c = idx >> 4, kc = (idx & 15) << 2;
            *(float4*)&Vs[c * 68 + kc] = *(const float4*)(V + (long long)(ct0 + c) * N_ + n0 + kc);
        }
        if (t < 64) {
            stats[t * 2]     = g_rowmax[b * N_ + n0 + t];
            stats[t * 2 + 1] = 1.0f / g_rowsum[b * N_ + n0 + t];
        }
        __syncthreads();

        // scores s[4][8] = Pn^T Pm  (K=64)
        float s[4][8];
#pragma unroll
        for (int i = 0; i < 4; i++)
#pragma unroll
            for (int j = 0; j < 8; j++) s[i][j] = 0.f;
#pragma unroll
        for (int k = 0; k < 64; k++) {
            float4 a  = *(float4*)&Pn[k * 68 + rs];
            float4 b0 = *(float4*)&Pm[k * 132 + cs];
            float4 b1 = *(float4*)&Pm[k * 132 + cs + 4];
            float av[4] = {a.x, a.y, a.z, a.w};
            float bv[8] = {b0.x, b0.y, b0.z, b0.w, b1.x, b1.y, b1.z, b1.w};
#pragma unroll
            for (int i = 0; i < 4; i++)
#pragma unroll
                for (int j = 0; j < 8; j++) s[i][j] += av[i] * bv[j];
        }
        // exp / rowsum -> Aexp
#pragma unroll
        for (int i = 0; i < 4; i++) {
            float mxv  = stats[(rs + i) * 2];
            float rinv = stats[(rs + i) * 2 + 1];
            float e[8];
#pragma unroll
            for (int j = 0; j < 8; j++) e[j] = __expf(s[i][j] - mxv) * rinv;
            *(float4*)&Aexp[(rs + i) * 132 + cs]     = make_float4(e[0], e[1], e[2], e[3]);
            *(float4*)&Aexp[(rs + i) * 132 + cs + 4] = make_float4(e[4], e[5], e[6], e[7]);
        }
        __syncthreads();

        if (chalf == 0 && t < 128) {
            float p = 0.f;
#pragma unroll
            for (int k = 0; k < 64; k++) p += Aexp[k * 132 + t];
            csum += p;
        }

        // acc += V[c,:] @ Aexp  (K=64)
#pragma unroll
        for (int k = 0; k < 64; k++) {
            float a[8];
#pragma unroll
            for (int i = 0; i < 8; i++) a[i] = Vs[(rg + i) * 68 + k];
            float4 b0 = *(float4*)&Aexp[k * 132 + cs];
            float4 b1 = *(float4*)&Aexp[k * 132 + cs + 4];
            float bv[8] = {b0.x, b0.y, b0.z, b0.w, b1.x, b1.y, b1.z, b1.w};
#pragma unroll
            for (int i = 0; i < 8; i++)
#pragma unroll
                for (int j = 0; j < 8; j++) acc[i][j] += a[i] * bv[j];
        }
    }

    float* Mp = g_M + (long long)b * C_ * N_;
#pragma unroll
    for (int i = 0; i < 8; i++) {
        *(float4*)&Mp[(long long)(ct0 + rg + i) * N_ + m0 + cs]     = make_float4(acc[i][0], acc[i][1], acc[i][2], acc[i][3]);
        *(float4*)&Mp[(long long)(ct0 + rg + i) * N_ + m0 + cs + 4] = make_float4(acc[i][4], acc[i][5], acc[i][6], acc[i][7]);
    }
    if (chalf == 0 && t < 128) g_colsum[b * N_ + m0 + t] = csum;
}

// ---------------- R = x - M / (1e-9 + colsum) ---------------------------------
__global__ __launch_bounds__(256) void residual_kernel(const float* __restrict__ x)
{
    int i   = blockIdx.x * blockDim.x + threadIdx.x;   // over B*C*N/4
    int lin = i * 4;
    int m   = lin & (N_ - 1);
    int b   = lin >> 20;                               // C_*N_ = 1<<20
    float4 xv = *(const float4*)(x + lin);
    float4 mv = *(const float4*)(g_M + lin);
    const float* cs = g_colsum + b * N_ + m;
    float4 r;
    r.x = xv.x - mv.x / (1e-9f + cs[0]);
    r.y = xv.y - mv.y / (1e-9f + cs[1]);
    r.z = xv.z - mv.z / (1e-9f + cs[2]);
    r.w = xv.w - mv.w / (1e-9f + cs[3]);
    *(float4*)(g_R + lin) = r;
}

// -------------------------------------------------------------------------------
#define ROWSTATS_SMEM ((2 * 64 * 132 + 128 * 32) * 4)
#define ATTN_SMEM     ((64 * 132 + 64 * 68 + 64 * 132 + 128 * 68 + 128) * 4)

extern "C" void kernel_launch(void* const* d_in, const int* in_sizes, int n_in,
                              void* d_out, int out_size)
{
    const float* x       = (const float*)d_in[0];
    const float* w_qk    = (const float*)d_in[1];
    const float* w_v     = (const float*)d_in[2];
    const float* b_v     = (const float*)d_in[3];
    const float* w_trans = (const float*)d_in[4];
    const float* b_trans = (const float*)d_in[5];
    const float* gamma   = (const float*)d_in[6];
    const float* beta    = (const float*)d_in[7];
    const float* mean    = (const float*)d_in[8];
    const float* var     = (const float*)d_in[9];
    float* out = (float*)d_out;

    cudaFuncSetAttribute(rowstats_kernel, cudaFuncAttributeMaxDynamicSharedMemorySize, ROWSTATS_SMEM);
    cudaFuncSetAttribute(attn_out_kernel, cudaFuncAttributeMaxDynamicSharedMemorySize, ATTN_SMEM);

    void *pP, *pV, *pR;
    cudaGetSymbolAddress(&pP, g_P);
    cudaGetSymbolAddress(&pV, g_V);
    cudaGetSymbolAddress(&pR, g_R);

    // P = w_qk @ x   (M=64)
    gemm_kernel<<<dim3(32, 1, 4), 256>>>(w_qk, x, (long long)C_ * N_,
                                         (float*)pP, (long long)CQ_ * N_,
                                         0, nullptr, nullptr, nullptr, nullptr, nullptr);
    // V = w_v @ x + b_v   (M=256)
    gemm_kernel<<<dim3(32, 4, 4), 256>>>(w_v, x, (long long)C_ * N_,
                                         (float*)pV, (long long)C_ * N_,
                                         1, b_v, nullptr, nullptr, nullptr, nullptr);
    // row softmax stats
    rowstats_kernel<<<dim3(32, 4), 256, ROWSTATS_SMEM>>>();
    // fused recompute + exp + V@A + colsum
    attn_out_kernel<<<dim3(2, 32, 4), 256, ATTN_SMEM>>>();
    // R = x - M/colsum
    residual_kernel<<<4096, 256>>>(x);
    // out = ReLU(BN(w_trans @ R + b_trans))
    gemm_kernel<<<dim3(32, 4, 4), 256>>>(w_trans, (const float*)pR, (long long)C_ * N_,
                                         out, (long long)C_ * N_,
                                         2, b_trans, gamma, beta, mean, var);
}

// round 4
// speedup vs baseline: 1.1456x; 1.1456x over previous
#include <cuda_runtime.h>
#include <math.h>
#include <stdint.h>

#define B_  4
#define C_  256
#define N_  4096
#define CQ_ 64

// ---------------- scratch (static __device__ — no allocations allowed) ---------
__device__ float g_P[B_*CQ_*N_];     // P = w_qk @ x          (4 MB)
__device__ float g_V[B_*C_*N_];      // V = w_v @ x + b_v     (16 MB)
__device__ float g_M[B_*C_*N_];      // unnormalized V @ A    (16 MB)
__device__ float g_R[B_*C_*N_];      // x - nf                (16 MB)
__device__ float g_rowmax[B_*N_];
__device__ float g_rowsum[B_*N_];
__device__ float g_colsum[B_*N_];

// ---------------- tf32 helpers --------------------------------------------------
__device__ __forceinline__ uint32_t f2tf(float x) {
    uint32_t r;
    asm("cvt.rna.tf32.f32 %0, %1;" : "=r"(r) : "f"(x));
    return r;
}
__device__ __forceinline__ float tf32r(float x) { return __uint_as_float(f2tf(x)); }

__device__ __forceinline__ void mma_tf32(float* d,
    uint32_t a0, uint32_t a1, uint32_t a2, uint32_t a3,
    uint32_t b0, uint32_t b1)
{
    asm("mma.sync.aligned.m16n8k8.row.col.f32.tf32.tf32.f32 "
        "{%0,%1,%2,%3}, {%4,%5,%6,%7}, {%8,%9}, {%0,%1,%2,%3};"
        : "+f"(d[0]), "+f"(d[1]), "+f"(d[2]), "+f"(d[3])
        : "r"(a0), "r"(a1), "r"(a2), "r"(a3), "r"(b0), "r"(b1));
}

// ---------------- generic batched SGEMM: C[b] = A(Mx256) * X[b](256xN_) --------
__global__ __launch_bounds__(256) void gemm_kernel(
    const float* __restrict__ A,
    const float* __restrict__ X, long long xstride,
    float* __restrict__ Co, long long cstride,
    int mode,
    const float* __restrict__ bias,
    const float* __restrict__ gamma, const float* __restrict__ beta,
    const float* __restrict__ mean,  const float* __restrict__ var)
{
    __shared__ float As[16][65];
    __shared__ float Bs[16][132];
    const int t  = threadIdx.x;
    const int n0 = blockIdx.x * 128;
    const int m0 = blockIdx.y * 64;
    const float* Xb = X + (long long)blockIdx.z * xstride;
    float*       Cb = Co + (long long)blockIdx.z * cstride;
    const int r0 = (t >> 5) << 3;
    const int c0 = (t & 31) << 2;

    float acc[8][4];
#pragma unroll
    for (int i = 0; i < 8; i++)
#pragma unroll
        for (int j = 0; j < 4; j++) acc[i][j] = 0.f;

    for (int k0 = 0; k0 < 256; k0 += 16) {
        {
            int row = t >> 2, kc = (t & 3) << 2;
            float4 v = *(const float4*)(A + (m0 + row) * 256 + k0 + kc);
            As[kc + 0][row] = v.x; As[kc + 1][row] = v.y;
            As[kc + 2][row] = v.z; As[kc + 3][row] = v.w;
        }
        {
            int kr = t >> 5, col = (t & 31) << 2;
            *(float4*)&Bs[kr][col]     = *(const float4*)(Xb + (long long)(k0 + kr)     * N_ + n0 + col);
            *(float4*)&Bs[kr + 8][col] = *(const float4*)(Xb + (long long)(k0 + kr + 8) * N_ + n0 + col);
        }
        __syncthreads();
#pragma unroll
        for (int k = 0; k < 16; k++) {
            float a[8];
#pragma unroll
            for (int i = 0; i < 8; i++) a[i] = As[k][r0 + i];
            float4 bv = *(float4*)&Bs[k][c0];
            float bb[4] = {bv.x, bv.y, bv.z, bv.w};
#pragma unroll
            for (int i = 0; i < 8; i++)
#pragma unroll
                for (int j = 0; j < 4; j++) acc[i][j] += a[i] * bb[j];
        }
        __syncthreads();
    }

#pragma unroll
    for (int i = 0; i < 8; i++) {
        int m = m0 + r0 + i;
        float v[4] = {acc[i][0], acc[i][1], acc[i][2], acc[i][3]};
        if (mode >= 1) {
            float bb = bias[m];
#pragma unroll
            for (int j = 0; j < 4; j++) v[j] += bb;
        }
        if (mode == 2) {
            float sc = gamma[m] * rsqrtf(var[m] + 1e-5f);
            float mu = mean[m], bt = beta[m];
#pragma unroll
            for (int j = 0; j < 4; j++) v[j] = fmaxf((v[j] - mu) * sc + bt, 0.f);
        }
        *(float4*)&Cb[(long long)m * N_ + n0 + c0] = make_float4(v[0], v[1], v[2], v[3]);
    }
}

// ---------------- pass 1: per-row online (max, sum) of scores = P^T P ----------
__global__ __launch_bounds__(256) void rowstats_kernel()
{
    extern __shared__ float sh[];
    float* Pn  = sh;
    float* Pm  = sh + 64 * 132;
    float* red = sh + 2 * 64 * 132;
    const int t  = threadIdx.x;
    const int n0 = blockIdx.x * 128;
    const int b  = blockIdx.y;
    const float* P = g_P + (long long)b * CQ_ * N_;

#pragma unroll
    for (int i = 0; i < 8; i++) {
        int idx = t + i * 256; int q = idx >> 5, col = (idx & 31) << 2;
        *(float4*)&Pn[q * 132 + col] = *(const float4*)(P + (long long)q * N_ + n0 + col);
    }

    const int r0 = (t >> 4) << 3;
    const int c0 = (t & 15) << 3;
    float mx[8], sm_[8];
#pragma unroll
    for (int i = 0; i < 8; i++) { mx[i] = -1e30f; sm_[i] = 0.f; }

    for (int m0 = 0; m0 < N_; m0 += 128) {
        __syncthreads();
#pragma unroll
        for (int i = 0; i < 8; i++) {
            int idx = t + i * 256; int q = idx >> 5, col = (idx & 31) << 2;
            *(float4*)&Pm[q * 132 + col] = *(const float4*)(P + (long long)q * N_ + m0 + col);
        }
        __syncthreads();

        float s[8][8];
#pragma unroll
        for (int i = 0; i < 8; i++)
#pragma unroll
            for (int j = 0; j < 8; j++) s[i][j] = 0.f;

#pragma unroll
        for (int k = 0; k < 64; k++) {
            float4 a0 = *(float4*)&Pn[k * 132 + r0];
            float4 a1 = *(float4*)&Pn[k * 132 + r0 + 4];
            float4 b0 = *(float4*)&Pm[k * 132 + c0];
            float4 b1 = *(float4*)&Pm[k * 132 + c0 + 4];
            float av[8] = {a0.x, a0.y, a0.z, a0.w, a1.x, a1.y, a1.z, a1.w};
            float bv[8] = {b0.x, b0.y, b0.z, b0.w, b1.x, b1.y, b1.z, b1.w};
#pragma unroll
            for (int i = 0; i < 8; i++)
#pragma unroll
                for (int j = 0; j < 8; j++) s[i][j] += av[i] * bv[j];
        }
#pragma unroll
        for (int i = 0; i < 8; i++) {
            float tm = s[i][0];
#pragma unroll
            for (int j = 1; j < 8; j++) tm = fmaxf(tm, s[i][j]);
            float nm = fmaxf(mx[i], tm);
            float add = 0.f;
#pragma unroll
            for (int j = 0; j < 8; j++) add += __expf(s[i][j] - nm);
            sm_[i] = sm_[i] * __expf(mx[i] - nm) + add;
            mx[i] = nm;
        }
    }
    __syncthreads();
#pragma unroll
    for (int i = 0; i < 8; i++) {
        red[(r0 + i) * 32 + (t & 15) * 2]     = mx[i];
        red[(r0 + i) * 32 + (t & 15) * 2 + 1] = sm_[i];
    }
    __syncthreads();
    if (t < 128) {
        float M = -1e30f, S = 0.f;
#pragma unroll
        for (int j = 0; j < 16; j++) {
            float m2 = red[t * 32 + j * 2], s2 = red[t * 32 + j * 2 + 1];
            float nm = fmaxf(M, m2);
            S = S * __expf(M - nm) + s2 * __expf(m2 - nm);
            M = nm;
        }
        g_rowmax[b * N_ + n0 + t] = M;
        g_rowsum[b * N_ + n0 + t] = S;
    }
}

// ---------------- pass 2: tensor-core fused attention ---------------------------
// grid (m-tile=64 tiles of 64, b=4). Block: full c=256 via two AV passes.
// Scores: 3xTF32 split precision. AV: single TF32 (rna-rounded operands).
__global__ __launch_bounds__(256, 1) void attn_out_kernel()
{
    extern __shared__ float sh[];
    float* Pm   = sh;                    // [64][68]   P[:, m-tile] fp32
    float* Pn   = Pm + 64 * 68;          // [64][132]  P[:, n-tile] fp32
    float* Ae   = Pn + 64 * 132;         // [128][68]  normalized attn (tf32-rounded)
    float* Vs   = Ae + 128 * 68;         // [128][132] V half-tile (tf32-rounded)
    float* smx  = Vs + 128 * 132;        // [128] rowmax
    float* sri  = smx + 128;             // [128] 1/rowsum
    float* part = sri + 128;             // [4][64] colsum partials

    const int t    = threadIdx.x;
    const int w    = t >> 5;
    const int lane = t & 31;
    const int g    = lane >> 2;      // groupID 0..7
    const int tig  = lane & 3;       // thread-in-group 0..3
    const int m0   = blockIdx.x * 64;
    const int b    = blockIdx.y;
    const int nb   = w * 16;         // warp row offset (n in phase A, c in phase B)

    const float* P = g_P + (long long)b * CQ_ * N_;
    const float* V = g_V + (long long)b * C_  * N_;

    // Pm: 64x64, persistent
#pragma unroll
    for (int i = 0; i < 4; i++) {
        int idx = t + i * 256; int r = idx >> 4, c4 = (idx & 15) << 2;
        *(float4*)&Pm[r * 68 + c4] = *(const float4*)(P + (long long)r * N_ + m0 + c4);
    }

    float accA[8][4], accB[8][4];
#pragma unroll
    for (int j = 0; j < 8; j++)
#pragma unroll
        for (int q = 0; q < 4; q++) { accA[j][q] = 0.f; accB[j][q] = 0.f; }
    float csum = 0.f;

    for (int n0 = 0; n0 < N_; n0 += 128) {
        __syncthreads();   // S1: previous-iteration consumers done

        // loads: Pn (fp32), Vs half 0 (rounded), stats
#pragma unroll
        for (int i = 0; i < 8; i++) {
            int idx = t + i * 256; int r = idx >> 5, c4 = (idx & 31) << 2;
            *(float4*)&Pn[r * 132 + c4] = *(const float4*)(P + (long long)r * N_ + n0 + c4);
        }
#pragma unroll
        for (int i = 0; i < 16; i++) {
            int idx = t + i * 256; int r = idx >> 5, c4 = (idx & 31) << 2;
            float4 v = *(const float4*)(V + (long long)r * N_ + n0 + c4);
            v.x = tf32r(v.x); v.y = tf32r(v.y); v.z = tf32r(v.z); v.w = tf32r(v.w);
            *(float4*)&Vs[r * 132 + c4] = v;
        }
        if (t < 128) {
            smx[t] = g_rowmax[b * N_ + n0 + t];
            sri[t] = 1.0f / g_rowsum[b * N_ + n0 + t];
        }
        __syncthreads();   // S2

        // ---- phase A: S[128 n][64 m] = Pn^T * Pm, 3xTF32 ----
        float s[8][4];
#pragma unroll
        for (int j = 0; j < 8; j++)
#pragma unroll
            for (int q = 0; q < 4; q++) s[j][q] = 0.f;

        for (int kc = 0; kc < 64; kc += 8) {
            float ar0 = Pn[(kc + tig)     * 132 + nb + g];
            float ar1 = Pn[(kc + tig)     * 132 + nb + g + 8];
            float ar2 = Pn[(kc + tig + 4) * 132 + nb + g];
            float ar3 = Pn[(kc + tig + 4) * 132 + nb + g + 8];
            uint32_t ah0 = f2tf(ar0), ah1 = f2tf(ar1), ah2 = f2tf(ar2), ah3 = f2tf(ar3);
            uint32_t al0 = __float_as_uint(ar0 - __uint_as_float(ah0));
            uint32_t al1 = __float_as_uint(ar1 - __uint_as_float(ah1));
            uint32_t al2 = __float_as_uint(ar2 - __uint_as_float(ah2));
            uint32_t al3 = __float_as_uint(ar3 - __uint_as_float(ah3));
#pragma unroll
            for (int j = 0; j < 8; j++) {
                float br0 = Pm[(kc + tig)     * 68 + j * 8 + g];
                float br1 = Pm[(kc + tig + 4) * 68 + j * 8 + g];
                uint32_t bh0 = f2tf(br0), bh1 = f2tf(br1);
                uint32_t bl0 = __float_as_uint(br0 - __uint_as_float(bh0));
                uint32_t bl1 = __float_as_uint(br1 - __uint_as_float(bh1));
                mma_tf32(s[j], ah0, ah1, ah2, ah3, bh0, bh1);
                mma_tf32(s[j], ah0, ah1, ah2, ah3, bl0, bl1);
                mma_tf32(s[j], al0, al1, al2, al3, bh0, bh1);
            }
        }

        // softmax (row-normalized), rounded to tf32, store to Ae
        {
            int r0 = nb + g, r1 = r0 + 8;
            float mx0 = smx[r0], ri0 = sri[r0];
            float mx1 = smx[r1], ri1 = sri[r1];
#pragma unroll
            for (int j = 0; j < 8; j++) {
                float e0 = tf32r(__expf(s[j][0] - mx0) * ri0);
                float e1 = tf32r(__expf(s[j][1] - mx0) * ri0);
                float e2 = tf32r(__expf(s[j][2] - mx1) * ri1);
                float e3 = tf32r(__expf(s[j][3] - mx1) * ri1);
                int col = j * 8 + 2 * tig;
                *(float2*)&Ae[r0 * 68 + col] = make_float2(e0, e1);
                *(float2*)&Ae[r1 * 68 + col] = make_float2(e2, e3);
            }
        }
        __syncthreads();   // S3: Ae ready

        // colsum partials + phase B pass 0 (c = 0..127)
        {
            int mq = t & 63, q = t >> 6;
            float p = 0.f;
#pragma unroll
            for (int nn = 0; nn < 32; nn++) p += Ae[(q * 32 + nn) * 68 + mq];
            part[q * 64 + mq] = p;
        }
        for (int nc = 0; nc < 128; nc += 8) {
            uint32_t a0 = __float_as_uint(Vs[(nb + g)     * 132 + nc + tig]);
            uint32_t a1 = __float_as_uint(Vs[(nb + g + 8) * 132 + nc + tig]);
            uint32_t a2 = __float_as_uint(Vs[(nb + g)     * 132 + nc + tig + 4]);
            uint32_t a3 = __float_as_uint(Vs[(nb + g + 8) * 132 + nc + tig + 4]);
#pragma unroll
            for (int j = 0; j < 8; j++) {
                uint32_t b0 = __float_as_uint(Ae[(nc + tig)     * 68 + j * 8 + g]);
                uint32_t b1 = __float_as_uint(Ae[(nc + tig + 4) * 68 + j * 8 + g]);
                mma_tf32(accA[j], a0, a1, a2, a3, b0, b1);
            }
        }
        __syncthreads();   // S4: Vs half 0 consumed, partials ready

        if (t < 64) csum += part[t] + part[64 + t] + part[128 + t] + part[192 + t];

        // load Vs half 1 (c = 128..255)
#pragma unroll
        for (int i = 0; i < 16; i++) {
            int idx = t + i * 256; int r = idx >> 5, c4 = (idx & 31) << 2;
            float4 v = *(const float4*)(V + (long long)(128 + r) * N_ + n0 + c4);
            v.x = tf32r(v.x); v.y = tf32r(v.y); v.z = tf32r(v.z); v.w = tf32r(v.w);
            *(float4*)&Vs[r * 132 + c4] = v;
        }
        __syncthreads();   // S5: Vs half 1 ready

        for (int nc = 0; nc < 128; nc += 8) {
            uint32_t a0 = __float_as_uint(Vs[(nb + g)     * 132 + nc + tig]);
            uint32_t a1 = __float_as_uint(Vs[(nb + g + 8) * 132 + nc + tig]);
            uint32_t a2 = __float_as_uint(Vs[(nb + g)     * 132 + nc + tig + 4]);
            uint32_t a3 = __float_as_uint(Vs[(nb + g + 8) * 132 + nc + tig + 4]);
#pragma unroll
            for (int j = 0; j < 8; j++) {
                uint32_t b0 = __float_as_uint(Ae[(nc + tig)     * 68 + j * 8 + g]);
                uint32_t b1 = __float_as_uint(Ae[(nc + tig + 4) * 68 + j * 8 + g]);
                mma_tf32(accB[j], a0, a1, a2, a3, b0, b1);
            }
        }
    }

    // ---- store M and colsum ----
    float* Mp = g_M + (long long)b * C_ * N_;
#pragma unroll
    for (int j = 0; j < 8; j++) {
        int c = nb + g;
        int m = m0 + j * 8 + 2 * tig;
        *(float2*)&Mp[(long long)c * N_ + m]         = make_float2(accA[j][0], accA[j][1]);
        *(float2*)&Mp[(long long)(c + 8) * N_ + m]   = make_float2(accA[j][2], accA[j][3]);
        *(float2*)&Mp[(long long)(c + 128) * N_ + m] = make_float2(accB[j][0], accB[j][1]);
        *(float2*)&Mp[(long long)(c + 136) * N_ + m] = make_float2(accB[j][2], accB[j][3]);
    }
    if (t < 64) g_colsum[b * N_ + m0 + t] = csum;
}

// ---------------- R = x - M / (1e-9 + colsum) ---------------------------------
__global__ __launch_bounds__(256) void residual_kernel(const float* __restrict__ x)
{
    int i   = blockIdx.x * blockDim.x + threadIdx.x;
    int lin = i * 4;
    int m   = lin & (N_ - 1);
    int b   = lin >> 20;
    float4 xv = *(const float4*)(x + lin);
    float4 mv = *(const float4*)(g_M + lin);
    const float* cs = g_colsum + b * N_ + m;
    float4 r;
    r.x = xv.x - mv.x / (1e-9f + cs[0]);
    r.y = xv.y - mv.y / (1e-9f + cs[1]);
    r.z = xv.z - mv.z / (1e-9f + cs[2]);
    r.w = xv.w - mv.w / (1e-9f + cs[3]);
    *(float4*)(g_R + lin) = r;
}

// -------------------------------------------------------------------------------
#define ROWSTATS_SMEM ((2 * 64 * 132 + 128 * 32) * 4)
#define ATTN_SMEM     ((64 * 68 + 64 * 132 + 128 * 68 + 128 * 132 + 128 + 128 + 256) * 4)

extern "C" void kernel_launch(void* const* d_in, const int* in_sizes, int n_in,
                              void* d_out, int out_size)
{
    const float* x       = (const float*)d_in[0];
    const float* w_qk    = (const float*)d_in[1];
    const float* w_v     = (const float*)d_in[2];
    const float* b_v     = (const float*)d_in[3];
    const float* w_trans = (const float*)d_in[4];
    const float* b_trans = (const float*)d_in[5];
    const float* gamma   = (const float*)d_in[6];
    const float* beta    = (const float*)d_in[7];
    const float* mean    = (const float*)d_in[8];
    const float* var     = (const float*)d_in[9];
    float* out = (float*)d_out;

    cudaFuncSetAttribute(rowstats_kernel, cudaFuncAttributeMaxDynamicSharedMemorySize, ROWSTATS_SMEM);
    cudaFuncSetAttribute(attn_out_kernel, cudaFuncAttributeMaxDynamicSharedMemorySize, ATTN_SMEM);

    void *pP, *pV, *pR;
    cudaGetSymbolAddress(&pP, g_P);
    cudaGetSymbolAddress(&pV, g_V);
    cudaGetSymbolAddress(&pR, g_R);

    // P = w_qk @ x   (M=64)
    gemm_kernel<<<dim3(32, 1, 4), 256>>>(w_qk, x, (long long)C_ * N_,
                                         (float*)pP, (long long)CQ_ * N_,
                                         0, nullptr, nullptr, nullptr, nullptr, nullptr);
    // V = w_v @ x + b_v   (M=256)
    gemm_kernel<<<dim3(32, 4, 4), 256>>>(w_v, x, (long long)C_ * N_,
                                         (float*)pV, (long long)C_ * N_,
                                         1, b_v, nullptr, nullptr, nullptr, nullptr);
    // row softmax stats (fp32)
    rowstats_kernel<<<dim3(32, 4), 256, ROWSTATS_SMEM>>>();
    // fused tensor-core attention: scores (3xTF32) + softmax + V@A (TF32) + colsum
    attn_out_kernel<<<dim3(64, 4), 256, ATTN_SMEM>>>();
    // R = x - M/colsum
    residual_kernel<<<4096, 256>>>(x);
    // out = ReLU(BN(w_trans @ R + b_trans))
    gemm_kernel<<<dim3(32, 4, 4), 256>>>(w_trans, (const float*)pR, (long long)C_ * N_,
                                         out, (long long)C_ * N_,
                                         2, b_trans, gamma, beta, mean, var);
}

// round 5
// speedup vs baseline: 2.1469x; 1.8741x over previous
#include <cuda_runtime.h>
#include <math.h>
#include <stdint.h>

#define B_  4
#define C_  256
#define N_  4096
#define CQ_ 64

// ---------------- scratch (static __device__ — no allocations allowed) ---------
__device__ float g_P[B_*CQ_*N_];     // P = w_qk @ x          (4 MB)
__device__ float g_V[B_*C_*N_];      // V = w_v @ x + b_v     (16 MB)
__device__ float g_M[B_*C_*N_];      // unnormalized V @ A    (16 MB)
__device__ float g_R[B_*C_*N_];      // x - nf                (16 MB)
__device__ float g_rowmax[B_*N_];
__device__ float g_rowsum[B_*N_];
__device__ float g_colsum[B_*N_];

// ---------------- tf32 helpers --------------------------------------------------
__device__ __forceinline__ uint32_t f2tf(float x) {
    uint32_t r;
    asm("cvt.rna.tf32.f32 %0, %1;" : "=r"(r) : "f"(x));
    return r;
}
__device__ __forceinline__ float tf32r(float x) { return __uint_as_float(f2tf(x)); }

__device__ __forceinline__ void mma_tf32(float* d,
    uint32_t a0, uint32_t a1, uint32_t a2, uint32_t a3,
    uint32_t b0, uint32_t b1)
{
    asm("mma.sync.aligned.m16n8k8.row.col.f32.tf32.tf32.f32 "
        "{%0,%1,%2,%3}, {%4,%5,%6,%7}, {%8,%9}, {%0,%1,%2,%3};"
        : "+f"(d[0]), "+f"(d[1]), "+f"(d[2]), "+f"(d[3])
        : "r"(a0), "r"(a1), "r"(a2), "r"(a3), "r"(b0), "r"(b1));
}

// ---------------- generic batched SGEMM: C[b] = A(Mx256) * X[b](256xN_) --------
__global__ __launch_bounds__(256) void gemm_kernel(
    const float* __restrict__ A,
    const float* __restrict__ X, long long xstride,
    float* __restrict__ Co, long long cstride,
    int mode,
    const float* __restrict__ bias,
    const float* __restrict__ gamma, const float* __restrict__ beta,
    const float* __restrict__ mean,  const float* __restrict__ var)
{
    __shared__ float As[16][65];
    __shared__ float Bs[16][132];
    const int t  = threadIdx.x;
    const int n0 = blockIdx.x * 128;
    const int m0 = blockIdx.y * 64;
    const float* Xb = X + (long long)blockIdx.z * xstride;
    float*       Cb = Co + (long long)blockIdx.z * cstride;
    const int r0 = (t >> 5) << 3;
    const int c0 = (t & 31) << 2;

    float acc[8][4];
#pragma unroll
    for (int i = 0; i < 8; i++)
#pragma unroll
        for (int j = 0; j < 4; j++) acc[i][j] = 0.f;

    for (int k0 = 0; k0 < 256; k0 += 16) {
        {
            int row = t >> 2, kc = (t & 3) << 2;
            float4 v = *(const float4*)(A + (m0 + row) * 256 + k0 + kc);
            As[kc + 0][row] = v.x; As[kc + 1][row] = v.y;
            As[kc + 2][row] = v.z; As[kc + 3][row] = v.w;
        }
        {
            int kr = t >> 5, col = (t & 31) << 2;
            *(float4*)&Bs[kr][col]     = *(const float4*)(Xb + (long long)(k0 + kr)     * N_ + n0 + col);
            *(float4*)&Bs[kr + 8][col] = *(const float4*)(Xb + (long long)(k0 + kr + 8) * N_ + n0 + col);
        }
        __syncthreads();
#pragma unroll
        for (int k = 0; k < 16; k++) {
            float a[8];
#pragma unroll
            for (int i = 0; i < 8; i++) a[i] = As[k][r0 + i];
            float4 bv = *(float4*)&Bs[k][c0];
            float bb[4] = {bv.x, bv.y, bv.z, bv.w};
#pragma unroll
            for (int i = 0; i < 8; i++)
#pragma unroll
                for (int j = 0; j < 4; j++) acc[i][j] += a[i] * bb[j];
        }
        __syncthreads();
    }

#pragma unroll
    for (int i = 0; i < 8; i++) {
        int m = m0 + r0 + i;
        float v[4] = {acc[i][0], acc[i][1], acc[i][2], acc[i][3]};
        if (mode >= 1) {
            float bb = bias[m];
#pragma unroll
            for (int j = 0; j < 4; j++) v[j] += bb;
        }
        if (mode == 2) {
            float sc = gamma[m] * rsqrtf(var[m] + 1e-5f);
            float mu = mean[m], bt = beta[m];
#pragma unroll
            for (int j = 0; j < 4; j++) v[j] = fmaxf((v[j] - mu) * sc + bt, 0.f);
        }
        *(float4*)&Cb[(long long)m * N_ + n0 + c0] = make_float4(v[0], v[1], v[2], v[3]);
    }
}

// ---------------- pass 1: rowstats via 3xTF32 MMA ------------------------------
// grid (32, 4), 256 threads. Block owns n-tile of 128 rows; streams m in 64-tiles.
// A-operand (Pn hi/lo splits) hoisted to registers for the whole m loop.
__global__ __launch_bounds__(256, 2) void rowstats_kernel()
{
    extern __shared__ float sh[];
    float* Pn  = sh;                 // [64][136] P[:, n-tile] fp32
    float* Pmh = Pn + 64 * 136;      // [64][72]  hi split of m-tile
    float* Pml = Pmh + 64 * 72;      // [64][72]  lo split

    const int t    = threadIdx.x;
    const int w    = t >> 5;
    const int lane = t & 31;
    const int g    = lane >> 2;
    const int tig  = lane & 3;
    const int n0   = blockIdx.x * 128;
    const int b    = blockIdx.y;
    const float* P = g_P + (long long)b * CQ_ * N_;

#pragma unroll
    for (int i = 0; i < 8; i++) {
        int idx = t + i * 256; int r = idx >> 5, c4 = (idx & 31) << 2;
        *(float4*)&Pn[r * 136 + c4] = *(const float4*)(P + (long long)r * N_ + n0 + c4);
    }
    __syncthreads();

    // hoist A fragments: rows n = w*16+g(+8), k = q (64) in 8 chunks
    uint32_t ah0[8], ah1[8], ah2[8], ah3[8];
    uint32_t al0[8], al1[8], al2[8], al3[8];
#pragma unroll
    for (int kc = 0; kc < 8; kc++) {
        float ar0 = Pn[(kc * 8 + tig)     * 136 + w * 16 + g];
        float ar1 = Pn[(kc * 8 + tig)     * 136 + w * 16 + g + 8];
        float ar2 = Pn[(kc * 8 + tig + 4) * 136 + w * 16 + g];
        float ar3 = Pn[(kc * 8 + tig + 4) * 136 + w * 16 + g + 8];
        ah0[kc] = f2tf(ar0); ah1[kc] = f2tf(ar1); ah2[kc] = f2tf(ar2); ah3[kc] = f2tf(ar3);
        al0[kc] = __float_as_uint(ar0 - __uint_as_float(ah0[kc]));
        al1[kc] = __float_as_uint(ar1 - __uint_as_float(ah1[kc]));
        al2[kc] = __float_as_uint(ar2 - __uint_as_float(ah2[kc]));
        al3[kc] = __float_as_uint(ar3 - __uint_as_float(ah3[kc]));
    }

    float mx0 = -1e30f, sm0 = 0.f, mx1 = -1e30f, sm1 = 0.f;

    for (int m0t = 0; m0t < N_; m0t += 64) {
        __syncthreads();
#pragma unroll
        for (int i = 0; i < 4; i++) {
            int idx = t + i * 256; int r = idx >> 4, c4 = (idx & 15) << 2;
            float4 v = *(const float4*)(P + (long long)r * N_ + m0t + c4);
            float4 h; h.x = tf32r(v.x); h.y = tf32r(v.y); h.z = tf32r(v.z); h.w = tf32r(v.w);
            float4 l; l.x = v.x - h.x; l.y = v.y - h.y; l.z = v.z - h.z; l.w = v.w - h.w;
            *(float4*)&Pmh[r * 72 + c4] = h;
            *(float4*)&Pml[r * 72 + c4] = l;
        }
        __syncthreads();

        float s[8][4];
#pragma unroll
        for (int j = 0; j < 8; j++)
#pragma unroll
            for (int q = 0; q < 4; q++) s[j][q] = 0.f;

#pragma unroll
        for (int kc = 0; kc < 8; kc++) {
#pragma unroll
            for (int j = 0; j < 8; j++) {
                int col = j * 8 + g;
                uint32_t bh0 = __float_as_uint(Pmh[(kc * 8 + tig)     * 72 + col]);
                uint32_t bh1 = __float_as_uint(Pmh[(kc * 8 + tig + 4) * 72 + col]);
                uint32_t bl0 = __float_as_uint(Pml[(kc * 8 + tig)     * 72 + col]);
                uint32_t bl1 = __float_as_uint(Pml[(kc * 8 + tig + 4) * 72 + col]);
                mma_tf32(s[j], ah0[kc], ah1[kc], ah2[kc], ah3[kc], bh0, bh1);
                mma_tf32(s[j], ah0[kc], ah1[kc], ah2[kc], ah3[kc], bl0, bl1);
                mma_tf32(s[j], al0[kc], al1[kc], al2[kc], al3[kc], bh0, bh1);
            }
        }

        // online (max, sum): rows r0 = w*16+g, r1 = r0+8; reduce over tig-quad
        float tm0 = -1e30f, tm1 = -1e30f;
#pragma unroll
        for (int j = 0; j < 8; j++) {
            tm0 = fmaxf(tm0, fmaxf(s[j][0], s[j][1]));
            tm1 = fmaxf(tm1, fmaxf(s[j][2], s[j][3]));
        }
        tm0 = fmaxf(tm0, __shfl_xor_sync(0xffffffffu, tm0, 1));
        tm0 = fmaxf(tm0, __shfl_xor_sync(0xffffffffu, tm0, 2));
        tm1 = fmaxf(tm1, __shfl_xor_sync(0xffffffffu, tm1, 1));
        tm1 = fmaxf(tm1, __shfl_xor_sync(0xffffffffu, tm1, 2));
        float nm0 = fmaxf(mx0, tm0), nm1 = fmaxf(mx1, tm1);
        float ad0 = 0.f, ad1 = 0.f;
#pragma unroll
        for (int j = 0; j < 8; j++) {
            ad0 += __expf(s[j][0] - nm0) + __expf(s[j][1] - nm0);
            ad1 += __expf(s[j][2] - nm1) + __expf(s[j][3] - nm1);
        }
        ad0 += __shfl_xor_sync(0xffffffffu, ad0, 1);
        ad0 += __shfl_xor_sync(0xffffffffu, ad0, 2);
        ad1 += __shfl_xor_sync(0xffffffffu, ad1, 1);
        ad1 += __shfl_xor_sync(0xffffffffu, ad1, 2);
        sm0 = sm0 * __expf(mx0 - nm0) + ad0; mx0 = nm0;
        sm1 = sm1 * __expf(mx1 - nm1) + ad1; mx1 = nm1;
    }

    if (tig == 0) {
        g_rowmax[b * N_ + n0 + w * 16 + g]     = mx0;
        g_rowsum[b * N_ + n0 + w * 16 + g]     = sm0;
        g_rowmax[b * N_ + n0 + w * 16 + g + 8] = mx1;
        g_rowsum[b * N_ + n0 + w * 16 + g + 8] = sm1;
    }
}

// ---------------- pass 2: tensor-core fused attention ---------------------------
// grid (64, 4), 512 threads (16 warps). Per n-tile of 128:
//   phase A: warps split (n-half=16 rows x m-half=32 cols) of S = Pn^T Pm (3xTF32)
//   phase B: warp w owns c-rows [16w,16w+16) over full m=64, single Vs pass (256 c)
// All fragment-load strides chosen conflict-free (Pn 136, Pm/Ae 72, Vs 132).
__global__ __launch_bounds__(512, 1) void attn_out_kernel()
{
    extern __shared__ float sh[];
    float* Pm   = sh;                    // [64][72]
    float* Pn   = Pm + 64 * 72;          // [64][136]
    float* Ae   = Pn + 64 * 136;         // [128][72]
    float* Vs   = Ae + 128 * 72;         // [256][132]
    float* smx  = Vs + 256 * 132;        // [128]
    float* sri  = smx + 128;             // [128]
    float* part = sri + 128;             // [8][64]

    const int t    = threadIdx.x;
    const int w    = t >> 5;
    const int lane = t & 31;
    const int g    = lane >> 2;
    const int tig  = lane & 3;
    const int wn   = w & 7;              // phase A n-slice
    const int mh   = w >> 3;             // phase A m-half
    const int m0   = blockIdx.x * 64;
    const int b    = blockIdx.y;

    const float* P = g_P + (long long)b * CQ_ * N_;
    const float* V = g_V + (long long)b * C_  * N_;

#pragma unroll
    for (int i = 0; i < 2; i++) {   // Pm 64x64, once
        int idx = t + i * 512; int r = idx >> 4, c4 = (idx & 15) << 2;
        *(float4*)&Pm[r * 72 + c4] = *(const float4*)(P + (long long)r * N_ + m0 + c4);
    }

    float acc[8][4];
#pragma unroll
    for (int j = 0; j < 8; j++)
#pragma unroll
        for (int q = 0; q < 4; q++) acc[j][q] = 0.f;
    float csum = 0.f;

    for (int n0 = 0; n0 < N_; n0 += 128) {
        __syncthreads();   // S1
        if (n0 && t < 64) {
#pragma unroll
            for (int q = 0; q < 8; q++) csum += part[q * 64 + t];
        }

#pragma unroll
        for (int i = 0; i < 4; i++) {   // Pn 64x128
            int idx = t + i * 512; int r = idx >> 5, c4 = (idx & 31) << 2;
            *(float4*)&Pn[r * 136 + c4] = *(const float4*)(P + (long long)r * N_ + n0 + c4);
        }
#pragma unroll
        for (int i = 0; i < 16; i++) {  // Vs 256x128 (tf32-rounded)
            int idx = t + i * 512; int r = idx >> 5, c4 = (idx & 31) << 2;
            float4 v = *(const float4*)(V + (long long)r * N_ + n0 + c4);
            v.x = tf32r(v.x); v.y = tf32r(v.y); v.z = tf32r(v.z); v.w = tf32r(v.w);
            *(float4*)&Vs[r * 132 + c4] = v;
        }
        if (t < 128) {
            smx[t] = g_rowmax[b * N_ + n0 + t];
            sri[t] = 1.0f / g_rowsum[b * N_ + n0 + t];
        }
        __syncthreads();   // S2

        // ---- phase A: s[4][4] = S[n-slice][m-half], 3xTF32 ----
        float s[4][4];
#pragma unroll
        for (int j = 0; j < 4; j++)
#pragma unroll
            for (int q = 0; q < 4; q++) s[j][q] = 0.f;

#pragma unroll
        for (int kc = 0; kc < 64; kc += 8) {
            float ar0 = Pn[(kc + tig)     * 136 + wn * 16 + g];
            float ar1 = Pn[(kc + tig)     * 136 + wn * 16 + g + 8];
            float ar2 = Pn[(kc + tig + 4) * 136 + wn * 16 + g];
            float ar3 = Pn[(kc + tig + 4) * 136 + wn * 16 + g + 8];
            uint32_t ah0 = f2tf(ar0), ah1 = f2tf(ar1), ah2 = f2tf(ar2), ah3 = f2tf(ar3);
            uint32_t al0 = __float_as_uint(ar0 - __uint_as_float(ah0));
            uint32_t al1 = __float_as_uint(ar1 - __uint_as_float(ah1));
            uint32_t al2 = __float_as_uint(ar2 - __uint_as_float(ah2));
            uint32_t al3 = __float_as_uint(ar3 - __uint_as_float(ah3));
#pragma unroll
            for (int j = 0; j < 4; j++) {
                int col = mh * 32 + j * 8 + g;
                float br0 = Pm[(kc + tig)     * 72 + col];
                float br1 = Pm[(kc + tig + 4) * 72 + col];
                uint32_t bh0 = f2tf(br0), bh1 = f2tf(br1);
                uint32_t bl0 = __float_as_uint(br0 - __uint_as_float(bh0));
                uint32_t bl1 = __float_as_uint(br1 - __uint_as_float(bh1));
                mma_tf32(s[j], ah0, ah1, ah2, ah3, bh0, bh1);
                mma_tf32(s[j], ah0, ah1, ah2, ah3, bl0, bl1);
                mma_tf32(s[j], al0, al1, al2, al3, bh0, bh1);
            }
        }

        // softmax -> Ae (tf32-rounded, normalized)
        {
            int r0 = wn * 16 + g, r1 = r0 + 8;
            float mxv0 = smx[r0], ri0 = sri[r0];
            float mxv1 = smx[r1], ri1 = sri[r1];
#pragma unroll
            for (int j = 0; j < 4; j++) {
                int col = mh * 32 + j * 8 + 2 * tig;
                float e0 = tf32r(__expf(s[j][0] - mxv0) * ri0);
                float e1 = tf32r(__expf(s[j][1] - mxv0) * ri0);
                float e2 = tf32r(__expf(s[j][2] - mxv1) * ri1);
                float e3 = tf32r(__expf(s[j][3] - mxv1) * ri1);
                *(float2*)&Ae[r0 * 72 + col] = make_float2(e0, e1);
                *(float2*)&Ae[r1 * 72 + col] = make_float2(e2, e3);
            }
        }
        __syncthreads();   // S3: Ae ready, Vs ready

        // colsum partials
        {
            int q = t >> 6, mq = t & 63;
            float p = 0.f;
#pragma unroll
            for (int nn = 0; nn < 16; nn++) p += Ae[(q * 16 + nn) * 72 + mq];
            part[q * 64 + mq] = p;
        }

        // ---- phase B: acc += V[c-strip,:] @ Ae, full c in one pass ----
#pragma unroll
        for (int nc = 0; nc < 128; nc += 8) {
            uint32_t a0 = __float_as_uint(Vs[(w * 16 + g)     * 132 + nc + tig]);
            uint32_t a1 = __float_as_uint(Vs[(w * 16 + g + 8) * 132 + nc + tig]);
            uint32_t a2 = __float_as_uint(Vs[(w * 16 + g)     * 132 + nc + tig + 4]);
            uint32_t a3 = __float_as_uint(Vs[(w * 16 + g + 8) * 132 + nc + tig + 4]);
#pragma unroll
            for (int j = 0; j < 8; j++) {
                uint32_t b0 = __float_as_uint(Ae[(nc + tig)     * 72 + j * 8 + g]);
                uint32_t b1 = __float_as_uint(Ae[(nc + tig + 4) * 72 + j * 8 + g]);
                mma_tf32(acc[j], a0, a1, a2, a3, b0, b1);
            }
        }
    }

    __syncthreads();
    if (t < 64) {
#pragma unroll
        for (int q = 0; q < 8; q++) csum += part[q * 64 + t];
        g_colsum[b * N_ + m0 + t] = csum;
    }

    float* Mp = g_M + (long long)b * C_ * N_;
    int c = w * 16 + g;
#pragma unroll
    for (int j = 0; j < 8; j++) {
        int m = m0 + j * 8 + 2 * tig;
        *(float2*)&Mp[(long long)c * N_ + m]       = make_float2(acc[j][0], acc[j][1]);
        *(float2*)&Mp[(long long)(c + 8) * N_ + m] = make_float2(acc[j][2], acc[j][3]);
    }
}

// ---------------- R = x - M / (1e-9 + colsum) ---------------------------------
__global__ __launch_bounds__(256) void residual_kernel(const float* __restrict__ x)
{
    int i   = blockIdx.x * blockDim.x + threadIdx.x;
    int lin = i * 4;
    int m   = lin & (N_ - 1);
    int b   = lin >> 20;
    float4 xv = *(const float4*)(x + lin);
    float4 mv = *(const float4*)(g_M + lin);
    const float* cs = g_colsum + b * N_ + m;
    float4 r;
    r.x = xv.x - mv.x / (1e-9f + cs[0]);
    r.y = xv.y - mv.y / (1e-9f + cs[1]);
    r.z = xv.z - mv.z / (1e-9f + cs[2]);
    r.w = xv.w - mv.w / (1e-9f + cs[3]);
    *(float4*)(g_R + lin) = r;
}

// -------------------------------------------------------------------------------
#define ROWSTATS_SMEM ((64 * 136 + 2 * 64 * 72) * 4)
#define ATTN_SMEM     ((64 * 72 + 64 * 136 + 128 * 72 + 256 * 132 + 128 + 128 + 512) * 4)

extern "C" void kernel_launch(void* const* d_in, const int* in_sizes, int n_in,
                              void* d_out, int out_size)
{
    const float* x       = (const float*)d_in[0];
    const float* w_qk    = (const float*)d_in[1];
    const float* w_v     = (const float*)d_in[2];
    const float* b_v     = (const float*)d_in[3];
    const float* w_trans = (const float*)d_in[4];
    const float* b_trans = (const float*)d_in[5];
    const float* gamma   = (const float*)d_in[6];
    const float* beta    = (const float*)d_in[7];
    const float* mean    = (const float*)d_in[8];
    const float* var     = (const float*)d_in[9];
    float* out = (float*)d_out;

    cudaFuncSetAttribute(rowstats_kernel, cudaFuncAttributeMaxDynamicSharedMemorySize, ROWSTATS_SMEM);
    cudaFuncSetAttribute(attn_out_kernel, cudaFuncAttributeMaxDynamicSharedMemorySize, ATTN_SMEM);

    void *pP, *pV, *pR;
    cudaGetSymbolAddress(&pP, g_P);
    cudaGetSymbolAddress(&pV, g_V);
    cudaGetSymbolAddress(&pR, g_R);

    // P = w_qk @ x   (M=64)
    gemm_kernel<<<dim3(32, 1, 4), 256>>>(w_qk, x, (long long)C_ * N_,
                                         (float*)pP, (long long)CQ_ * N_,
                                         0, nullptr, nullptr, nullptr, nullptr, nullptr);
    // V = w_v @ x + b_v   (M=256)
    gemm_kernel<<<dim3(32, 4, 4), 256>>>(w_v, x, (long long)C_ * N_,
                                         (float*)pV, (long long)C_ * N_,
                                         1, b_v, nullptr, nullptr, nullptr, nullptr);
    // row softmax stats (3xTF32 mma)
    rowstats_kernel<<<dim3(32, 4), 256, ROWSTATS_SMEM>>>();
    // fused tensor-core attention
    attn_out_kernel<<<dim3(64, 4), 512, ATTN_SMEM>>>();
    // R = x - M/colsum
    residual_kernel<<<4096, 256>>>(x);
    // out = ReLU(BN(w_trans @ R + b_trans))
    gemm_kernel<<<dim3(32, 4, 4), 256>>>(w_trans, (const float*)pR, (long long)C_ * N_,
                                         out, (long long)C_ * N_,
                                         2, b_trans, gamma, beta, mean, var);
}